// round 1
// baseline (speedup 1.0000x reference)
#include <cuda_runtime.h>

// ---------------- problem constants ----------------
#define NB   32      // batch
#define C_R  32      // residual channels
#define C_C  32      // conv channels
#define C_S  64      // skip channels
#define NV   500     // nodes
#define NT   64      // input time
#define NK   52      // time after dilated inception
#define NMCOL (NB*C_C*NK)   // 53248 = GEMM N dim (node-major h columns)
#define APAD 512            // padded adjacency row stride
#define HVEC (C_C*NK)       // 1664 floats per (n,b)
#define CNT_PER_B (C_C*NV*NK)  // 832000

// ---------------- device scratch ----------------
__device__ float g_a1[NV*APAD];
__device__ float g_a2[NV*APAD];
__device__ float g_Wf[C_C*C_R*7];
__device__ float g_Wg[C_C*C_R*7];
__device__ float g_fbias[C_C];
__device__ float g_gbias[C_C];
__device__ float g_h  [NV*NB*C_C*NK];
__device__ float g_h1a[NV*NB*C_C*NK];
__device__ float g_h2a[NV*NB*C_C*NK];
__device__ float g_h1b[NV*NB*C_C*NK];
__device__ float g_h2b[NV*NB*C_C*NK];
__device__ float g_xo [NB*C_C*NV*NK];
__device__ float g_stats[2*NB];

// ---------------- prep: pack unified 7-tap weights, zero stats ----------------
__global__ void pack_kernel(const float* __restrict__ fw2, const float* __restrict__ fw3,
                            const float* __restrict__ fw6, const float* __restrict__ fw7,
                            const float* __restrict__ fb2, const float* __restrict__ fb3,
                            const float* __restrict__ fb6, const float* __restrict__ fb7,
                            const float* __restrict__ gw2, const float* __restrict__ gw3,
                            const float* __restrict__ gw6, const float* __restrict__ gw7,
                            const float* __restrict__ gb2, const float* __restrict__ gb3,
                            const float* __restrict__ gb6, const float* __restrict__ gb7)
{
    int tid = threadIdx.x;
    if (tid < 2*NB) g_stats[tid] = 0.f;
    for (int e = tid; e < C_C*C_R*7; e += blockDim.x) {
        int j  = e % 7;
        int i  = (e / 7) % C_R;
        int o  = e / (7*C_R);
        int br = o >> 3, oo = o & 7;
        int k  = (br==0)?2:(br==1)?3:(br==2)?6:7;
        int j0 = 7 - k;
        float vf = 0.f, vg = 0.f;
        if (j >= j0) {
            int si = (oo*C_R + i)*k + (j - j0);
            const float* fw = (br==0)?fw2:(br==1)?fw3:(br==2)?fw6:fw7;
            const float* gw = (br==0)?gw2:(br==1)?gw3:(br==2)?gw6:gw7;
            vf = fw[si]; vg = gw[si];
        }
        g_Wf[e] = vf; g_Wg[e] = vg;
    }
    if (tid < C_C) {
        int br = tid >> 3, oo = tid & 7;
        const float* fb = (br==0)?fb2:(br==1)?fb3:(br==2)?fb6:fb7;
        const float* gb = (br==0)?gb2:(br==1)?gb3:(br==2)?gb6:gb7;
        g_fbias[tid] = fb[oo]; g_gbias[tid] = gb[oo];
    }
}

// ---------------- normalized adjacencies (row-stride padded to 512, zero pad) ----------------
__global__ void adj_kernel(const float* __restrict__ adp)
{
    int v = blockIdx.x % NV;
    int which = blockIdx.x / NV;   // 0: a1 (rows of adp), 1: a2 (rows of adp^T)
    __shared__ float red[256];
    float s = 0.f;
    for (int w = threadIdx.x; w < NV; w += 256)
        s += (which == 0) ? adp[v*NV + w] : adp[w*NV + v];
    red[threadIdx.x] = s; __syncthreads();
    for (int st = 128; st > 0; st >>= 1) {
        if (threadIdx.x < st) red[threadIdx.x] += red[threadIdx.x + st];
        __syncthreads();
    }
    float inv = 1.f / (red[0] + 1.f);   // +1 for identity
    float* dst = (which == 0) ? g_a1 : g_a2;
    for (int w = threadIdx.x; w < APAD; w += 256) {
        float val = 0.f;
        if (w < NV) {
            val = (which == 0) ? adp[v*NV + w] : adp[w*NV + v];
            if (w == v) val += 1.f;
            val *= inv;
        }
        dst[v*APAD + w] = val;
    }
}

// ---------------- fused dilated inception (f,g) + tanh*sigmoid gating ----------------
// h stored node-major: h[((n*NB+b)*C_C + o)*NK + t]
#define INCEPT_SMEM ((4*32*72 + 2*7168 + 64)*4)
__global__ __launch_bounds__(256) void incept_kernel(const float* __restrict__ x)
{
    extern __shared__ __align__(16) float sm[];
    float* xs  = sm;                 // 4 * 32 * 72
    float* Wfs = xs + 4*32*72;       // 7168
    float* Wgs = Wfs + 7168;         // 7168
    float* fbs = Wgs + 7168;         // 32
    float* gbs = fbs + 32;           // 32
    int tid = threadIdx.x;

    for (int e = tid; e < 7168; e += 256) { Wfs[e] = g_Wf[e]; Wgs[e] = g_Wg[e]; }
    if (tid < 32) { fbs[tid] = g_fbias[tid]; gbs[tid] = g_gbias[tid]; }

    int p0 = blockIdx.x * 4;
    #pragma unroll
    for (int it = 0; it < 8; it++) {
        int lin = tid + it*256;        // 2048 float4 total
        int sub = lin >> 9;
        int rem = lin & 511;
        int i   = rem >> 4;
        int tq  = rem & 15;
        int p = p0 + sub;
        int n = p >> 5, b = p & 31;
        float4 v = *(const float4*)&x[((b*C_R + i)*NV + n)*NT + tq*4];
        *(float4*)&xs[(sub*32 + i)*72 + tq*4] = v;
    }
    __syncthreads();

    int sub = tid >> 6;
    int oq  = (tid >> 3) & 7;
    int tg  = tid & 7;

    float accf[4][7], accg[4][7];
    #pragma unroll
    for (int m = 0; m < 4; m++)
        #pragma unroll
        for (int s = 0; s < 7; s++) { accf[m][s] = 0.f; accg[m][s] = 0.f; }

    const float* xb = &xs[sub*32*72];
    for (int i = 0; i < 32; i++) {
        const float* xr = xb + i*72;
        #pragma unroll
        for (int j = 0; j < 7; j++) {
            float xv[7];
            #pragma unroll
            for (int s = 0; s < 7; s++) xv[s] = xr[tg + 8*s + 2*j];
            #pragma unroll
            for (int m = 0; m < 4; m++) {
                float wf = Wfs[(oq + 8*m)*224 + i*7 + j];
                float wg = Wgs[(oq + 8*m)*224 + i*7 + j];
                #pragma unroll
                for (int s = 0; s < 7; s++) {
                    accf[m][s] = fmaf(xv[s], wf, accf[m][s]);
                    accg[m][s] = fmaf(xv[s], wg, accg[m][s]);
                }
            }
        }
    }

    int p = p0 + sub;
    int n = p >> 5, b = p & 31;
    float* hout = &g_h[(n*NB + b)*HVEC];
    #pragma unroll
    for (int m = 0; m < 4; m++) {
        int o = oq + 8*m;
        #pragma unroll
        for (int s = 0; s < 7; s++) {
            int t = tg + 8*s;
            if (t < NK) {
                float f  = tanhf(accf[m][s] + fbs[o]);
                float gz = accg[m][s] + gbs[o];
                float gg = 1.f / (1.f + __expf(-gz));
                hout[o*NK + t] = f * gg;
            }
        }
    }
}

// ---------------- skip conv: s[b,cs,n] = <h[(n,b),:], skip_w[cs,:]> + skip_b ----------------
#define SKIP_SMEM (8*HVEC*4)
__global__ __launch_bounds__(256) void skip_kernel(const float* __restrict__ skipw,
                                                   const float* __restrict__ skipb,
                                                   float* __restrict__ sout)
{
    extern __shared__ __align__(16) float hs[];   // [8][1664]
    int tid = threadIdx.x;
    int b  = blockIdx.y;
    int n0 = blockIdx.x * 8;

    for (int lin = tid; lin < 8*416; lin += 256) {
        int nn = lin / 416, q = lin % 416;
        int n = n0 + nn;
        float4 v = make_float4(0.f, 0.f, 0.f, 0.f);
        if (n < NV) v = *(const float4*)&g_h[(n*NB + b)*HVEC + q*4];
        *(float4*)&hs[nn*HVEC + q*4] = v;
    }
    __syncthreads();

    int warp = tid >> 5, lane = tid & 31;
    int n = n0 + warp;
    if (n >= NV) return;
    const float4* hv = (const float4*)&hs[warp*HVEC];
    for (int cs = 0; cs < C_S; cs++) {
        const float4* wv = (const float4*)&skipw[cs*HVEC];
        float acc = 0.f;
        #pragma unroll
        for (int q = 0; q < 13; q++) {
            float4 w4 = wv[q*32 + lane];
            float4 h4 = hv[q*32 + lane];
            acc = fmaf(w4.x, h4.x, acc);
            acc = fmaf(w4.y, h4.y, acc);
            acc = fmaf(w4.z, h4.z, acc);
            acc = fmaf(w4.w, h4.w, acc);
        }
        #pragma unroll
        for (int off = 16; off > 0; off >>= 1)
            acc += __shfl_down_sync(0xffffffffu, acc, off);
        if (lane == 0) sout[(b*C_S + cs)*NV + n] = acc + skipb[cs];
    }
}

// ---------------- graph propagation GEMM: Hout = 0.05*g_h + 0.95*(A @ Hin) ----------------
// A: [500 x 512-padded], Hin/Hout: [500 x 53248]
__global__ __launch_bounds__(256) void prop_kernel(int step)
{
    const float* A; const float* Hin; float* Hout;
    if (blockIdx.z == 0) { A = g_a1; Hin = (step == 1) ? g_h : g_h1a; Hout = (step == 1) ? g_h1a : g_h2a; }
    else                 { A = g_a2; Hin = (step == 1) ? g_h : g_h1b; Hout = (step == 1) ? g_h1b : g_h2b; }

    __shared__ __align__(16) float As[16][132];
    __shared__ __align__(16) float Bs[16][128];

    int tid = threadIdx.x;
    int ty = tid >> 4, tx = tid & 15;
    int vbase = blockIdx.y * 128;
    int nbase = blockIdx.x * 128;

    float acc[8][8];
    #pragma unroll
    for (int i = 0; i < 8; i++)
        #pragma unroll
        for (int j = 0; j < 8; j++) acc[i][j] = 0.f;

    for (int kk = 0; kk < APAD; kk += 16) {
        #pragma unroll
        for (int it = 0; it < 2; it++) {
            int lin = tid + it*256;
            int row = lin >> 2;
            int kq  = (lin & 3) * 4;
            int v = vbase + row;
            float4 val = make_float4(0.f, 0.f, 0.f, 0.f);
            if (v < NV) val = *(const float4*)&A[v*APAD + kk + kq];
            As[kq+0][row] = val.x; As[kq+1][row] = val.y;
            As[kq+2][row] = val.z; As[kq+3][row] = val.w;
        }
        #pragma unroll
        for (int it = 0; it < 2; it++) {
            int lin = tid + it*256;
            int krow = lin >> 5;
            int nq   = (lin & 31) * 4;
            int kg = kk + krow;
            float4 val = make_float4(0.f, 0.f, 0.f, 0.f);
            if (kg < NV) val = *(const float4*)&Hin[kg*NMCOL + nbase + nq];
            *(float4*)&Bs[krow][nq] = val;
        }
        __syncthreads();
        #pragma unroll
        for (int k = 0; k < 16; k++) {
            float ra[8], rb[8];
            *(float4*)&ra[0] = *(float4*)&As[k][ty*8];
            *(float4*)&ra[4] = *(float4*)&As[k][ty*8 + 4];
            *(float4*)&rb[0] = *(float4*)&Bs[k][tx*8];
            *(float4*)&rb[4] = *(float4*)&Bs[k][tx*8 + 4];
            #pragma unroll
            for (int i = 0; i < 8; i++)
                #pragma unroll
                for (int j = 0; j < 8; j++)
                    acc[i][j] = fmaf(ra[i], rb[j], acc[i][j]);
        }
        __syncthreads();
    }

    #pragma unroll
    for (int i = 0; i < 8; i++) {
        int v = vbase + ty*8 + i;
        if (v < NV) {
            int base = v*NMCOL + nbase + tx*8;
            #pragma unroll
            for (int jq = 0; jq < 2; jq++) {
                float4 hb = *(const float4*)&g_h[base + jq*4];
                float4 o;
                o.x = fmaf(0.95f, acc[i][jq*4+0], 0.05f*hb.x);
                o.y = fmaf(0.95f, acc[i][jq*4+1], 0.05f*hb.y);
                o.z = fmaf(0.95f, acc[i][jq*4+2], 0.05f*hb.z);
                o.w = fmaf(0.95f, acc[i][jq*4+3], 0.05f*hb.w);
                *(float4*)&Hout[base + jq*4] = o;
            }
        }
    }
}

// ---------------- combine: xo = conv1x1(h,h1a,h2a;gc1) + conv1x1(h,h1b,h2b;gc2) + residual ----------------
// also accumulates per-batch sum / sumsq for LayerNorm
#define COMB_SMEM ((4*5*32*56 + 5*1024 + 32)*4)
__global__ __launch_bounds__(256) void combine_kernel(const float* __restrict__ x,
                                                      const float* __restrict__ gc1w,
                                                      const float* __restrict__ gc1b,
                                                      const float* __restrict__ gc2w,
                                                      const float* __restrict__ gc2b)
{
    extern __shared__ __align__(16) float sm[];
    float* ts = sm;                      // [4 sub][5 tensors][32 c'][56]
    float* ws = sm + 4*5*32*56;          // [5][cp][c] (cp-major to avoid bank conflicts)
    float* bs = ws + 5*1024;             // 32
    int tid = threadIdx.x;
    int v  = blockIdx.x;
    int bg = blockIdx.y;

    for (int e = tid; e < 1024; e += 256) {
        int cp = e >> 5, c = e & 31;
        ws[0*1024 + cp*32 + c] = gc1w[c*96 + cp] + gc2w[c*96 + cp];
        ws[1*1024 + cp*32 + c] = gc1w[c*96 + 32 + cp];
        ws[2*1024 + cp*32 + c] = gc1w[c*96 + 64 + cp];
        ws[3*1024 + cp*32 + c] = gc2w[c*96 + 32 + cp];
        ws[4*1024 + cp*32 + c] = gc2w[c*96 + 64 + cp];
    }
    if (tid < 32) bs[tid] = gc1b[tid] + gc2b[tid];

    #pragma unroll
    for (int t = 0; t < 5; t++) {
        const float* src = (t==0)?g_h:(t==1)?g_h1a:(t==2)?g_h2a:(t==3)?g_h1b:g_h2b;
        for (int lin = tid; lin < 4*32*13; lin += 256) {
            int lq = lin % 13;
            int r  = lin / 13;
            int cp = r & 31;
            int sub = r >> 5;
            int b = bg*4 + sub;
            float4 val = *(const float4*)&src[(v*NB + b)*HVEC + cp*NK + lq*4];
            *(float4*)&ts[((sub*5 + t)*32 + cp)*56 + lq*4] = val;
        }
    }
    __syncthreads();

    int sub = tid >> 6;
    int cq  = (tid >> 3) & 7;
    int lg  = tid & 7;
    int b = bg*4 + sub;

    float acc[4][7];
    #pragma unroll
    for (int m = 0; m < 4; m++)
        #pragma unroll
        for (int s = 0; s < 7; s++) acc[m][s] = 0.f;

    const float* tb = &ts[sub*5*32*56];
    for (int cp = 0; cp < 32; cp++) {
        float w0[4], w1[4], w2[4], w3[4], w4[4];
        #pragma unroll
        for (int m = 0; m < 4; m++) {
            int c = cq + 8*m;
            w0[m] = ws[0*1024 + cp*32 + c];
            w1[m] = ws[1*1024 + cp*32 + c];
            w2[m] = ws[2*1024 + cp*32 + c];
            w3[m] = ws[3*1024 + cp*32 + c];
            w4[m] = ws[4*1024 + cp*32 + c];
        }
        #pragma unroll
        for (int s = 0; s < 7; s++) {
            int l = lg + 8*s;
            float v0 = tb[(0*32 + cp)*56 + l];
            float v1 = tb[(1*32 + cp)*56 + l];
            float v2 = tb[(2*32 + cp)*56 + l];
            float v3 = tb[(3*32 + cp)*56 + l];
            float v4 = tb[(4*32 + cp)*56 + l];
            #pragma unroll
            for (int m = 0; m < 4; m++) {
                acc[m][s] = fmaf(w0[m], v0, acc[m][s]);
                acc[m][s] = fmaf(w1[m], v1, acc[m][s]);
                acc[m][s] = fmaf(w2[m], v2, acc[m][s]);
                acc[m][s] = fmaf(w3[m], v3, acc[m][s]);
                acc[m][s] = fmaf(w4[m], v4, acc[m][s]);
            }
        }
    }

    float psum = 0.f, psq = 0.f;
    #pragma unroll
    for (int m = 0; m < 4; m++) {
        int c = cq + 8*m;
        #pragma unroll
        for (int s = 0; s < 7; s++) {
            int l = lg + 8*s;
            if (l < NK) {
                float val = acc[m][s] + bs[c] + x[((b*C_R + c)*NV + v)*NT + 12 + l];
                g_xo[((b*C_C + c)*NV + v)*NK + l] = val;
                psum += val;
                psq  = fmaf(val, val, psq);
            }
        }
    }
    #pragma unroll
    for (int off = 16; off > 0; off >>= 1) {
        psum += __shfl_down_sync(0xffffffffu, psum, off);
        psq  += __shfl_down_sync(0xffffffffu, psq,  off);
    }
    if ((tid & 31) == 0) {
        atomicAdd(&g_stats[2*b],     psum);
        atomicAdd(&g_stats[2*b + 1], psq);
    }
}

// ---------------- LayerNorm apply ----------------
__global__ __launch_bounds__(256) void norm_kernel(const int* __restrict__ idx,
                                                   const float* __restrict__ lnw,
                                                   const float* __restrict__ lnb,
                                                   float* __restrict__ out)
{
    int gid = blockIdx.x * 256 + threadIdx.x;   // one float4 each; 6,656,000 total
    int lq  = gid % 13;
    int row = gid / 13;                         // = ((b*32 + c)*500 + v)
    int v = row % NV;
    int c = (row / NV) % C_C;
    int b = row / (C_C*NV);

    float s1 = g_stats[2*b], s2 = g_stats[2*b + 1];
    float mean = s1 * (1.f / (float)CNT_PER_B);
    float var  = s2 * (1.f / (float)CNT_PER_B) - mean*mean;
    float rstd = rsqrtf(var + 1e-5f);
    int nidx = idx[v];

    float4 xo = *(const float4*)&g_xo[row*NK + lq*4];
    float4 w4 = *(const float4*)&lnw[(c*NV + nidx)*NK + lq*4];
    float4 b4 = *(const float4*)&lnb[(c*NV + nidx)*NK + lq*4];
    float4 o;
    o.x = (xo.x - mean)*rstd*w4.x + b4.x;
    o.y = (xo.y - mean)*rstd*w4.y + b4.y;
    o.z = (xo.z - mean)*rstd*w4.z + b4.z;
    o.w = (xo.w - mean)*rstd*w4.w + b4.w;
    *(float4*)&out[row*NK + lq*4] = o;
}

// ---------------- launch ----------------
extern "C" void kernel_launch(void* const* d_in, const int* in_sizes, int n_in,
                              void* d_out, int out_size)
{
    const float* x = (const float*)d_in[0];
    int ia = (in_sizes[1] == NV*NV) ? 1 : 2;   // adp vs idx position
    const float* adp = (const float*)d_in[ia];
    const int*   idx = (const int*)d_in[3 - ia];
    const float* fw2 = (const float*)d_in[3];
    const float* fb2 = (const float*)d_in[4];
    const float* fw3 = (const float*)d_in[5];
    const float* fb3 = (const float*)d_in[6];
    const float* fw6 = (const float*)d_in[7];
    const float* fb6 = (const float*)d_in[8];
    const float* fw7 = (const float*)d_in[9];
    const float* fb7 = (const float*)d_in[10];
    const float* gw2 = (const float*)d_in[11];
    const float* gb2 = (const float*)d_in[12];
    const float* gw3 = (const float*)d_in[13];
    const float* gb3 = (const float*)d_in[14];
    const float* gw6 = (const float*)d_in[15];
    const float* gb6 = (const float*)d_in[16];
    const float* gw7 = (const float*)d_in[17];
    const float* gb7 = (const float*)d_in[18];
    const float* skipw = (const float*)d_in[19];
    const float* skipb = (const float*)d_in[20];
    const float* gc1w  = (const float*)d_in[21];
    const float* gc1b  = (const float*)d_in[22];
    const float* gc2w  = (const float*)d_in[23];
    const float* gc2b  = (const float*)d_in[24];
    const float* lnw   = (const float*)d_in[25];
    const float* lnb   = (const float*)d_in[26];
    float* out = (float*)d_out;
    float* xn_out = out;                            // [32,32,500,52]
    float* s_out  = out + NB*C_C*NV*NK;             // [32,64,500,1]

    cudaFuncSetAttribute(incept_kernel,  cudaFuncAttributeMaxDynamicSharedMemorySize, INCEPT_SMEM);
    cudaFuncSetAttribute(skip_kernel,    cudaFuncAttributeMaxDynamicSharedMemorySize, SKIP_SMEM);
    cudaFuncSetAttribute(combine_kernel, cudaFuncAttributeMaxDynamicSharedMemorySize, COMB_SMEM);

    pack_kernel<<<1, 256>>>(fw2, fw3, fw6, fw7, fb2, fb3, fb6, fb7,
                            gw2, gw3, gw6, gw7, gb2, gb3, gb6, gb7);
    adj_kernel<<<2*NV, 256>>>(adp);
    incept_kernel<<<(NV*NB)/4, 256, INCEPT_SMEM>>>(x);
    skip_kernel<<<dim3(63, NB), 256, SKIP_SMEM>>>(skipw, skipb, s_out);
    prop_kernel<<<dim3(NMCOL/128, 4, 2), 256>>>(1);
    prop_kernel<<<dim3(NMCOL/128, 4, 2), 256>>>(2);
    combine_kernel<<<dim3(NV, 8), 256, COMB_SMEM>>>(x, gc1w, gc1b, gc2w, gc2b);
    norm_kernel<<<26000, 256>>>(idx, lnw, lnb, xn_out);
}